// round 9
// baseline (speedup 1.0000x reference)
#include <cuda_runtime.h>
#include <stdint.h>

// QuantizationLayer: out[i, 4j + k] = bit (3-k) of rint(x[i,j]*16 - 0.5), as f32.
// Controlled experiment: R6's exact per-thread footprint (4 elements/thread,
// TPB=256, cacheable loads, .cs stores, one-shot grid) with the ONLY change
// being store width 128 -> 256 bit (st.global.cs.v8.f32). Distinguishes
// "256-bit stores hurt graph replay" from "R7 bench was noise/shape".

#define TPB 256
#define PAIRS 2   // float2 pairs per thread -> 4 elements/thread (same as R6)

__device__ __forceinline__ void stg256_cs(float* p, const float* v)
{
    asm volatile("st.global.cs.v8.f32 [%0], {%1,%2,%3,%4,%5,%6,%7,%8};"
                 :: "l"(p),
                    "f"(v[0]), "f"(v[1]), "f"(v[2]), "f"(v[3]),
                    "f"(v[4]), "f"(v[5]), "f"(v[6]), "f"(v[7])
                 : "memory");
}

__device__ __forceinline__ void quant4(float x, float* b)
{
    // Match JAX exactly: two separate f32 ops, round-half-even.
    float t = x * 16.0f;
    t = t - 0.5f;
    int num = (int)rintf(t);
    num &= 255;  // uint8 wraparound emulation (no-op for x in [0,1))

    b[0] = (num & 8) ? 1.0f : 0.0f;
    b[1] = (num & 4) ? 1.0f : 0.0f;
    b[2] = (num & 2) ? 1.0f : 0.0f;
    b[3] = (num & 1) ? 1.0f : 0.0f;
}

__global__ void __launch_bounds__(TPB, 8)
quant_bits_kernel(const float2* __restrict__ x2, float* __restrict__ out, int n_pairs)
{
    int base = blockIdx.x * (TPB * PAIRS) + threadIdx.x;

    // Front-batched cacheable 64-bit loads (L2-resident across replays).
    float2 v[PAIRS];
#pragma unroll
    for (int u = 0; u < PAIRS; u++) {
        int p = base + u * TPB;
        v[u] = (p < n_pairs) ? x2[p] : make_float2(0.0f, 0.0f);
    }

#pragma unroll
    for (int u = 0; u < PAIRS; u++) {
        int p = base + u * TPB;
        if (p >= n_pairs) continue;

        float bits[8];
        quant4(v[u].x, bits);
        quant4(v[u].y, bits + 4);

        stg256_cs(out + (size_t)p * 8, bits);   // 32B/lane, 1KB dense per warp
    }
}

extern "C" void kernel_launch(void* const* d_in, const int* in_sizes, int n_in,
                              void* d_out, int out_size)
{
    const float2* x2 = (const float2*)d_in[0];
    float* out = (float*)d_out;
    int n_pairs = in_sizes[0] / 2;   // 8388608 / 2 = 4194304

    int blocks = (n_pairs + TPB * PAIRS - 1) / (TPB * PAIRS);
    quant_bits_kernel<<<blocks, TPB>>>(x2, out, n_pairs);
}

// round 11
// speedup vs baseline: 1.1633x; 1.1633x over previous
#include <cuda_runtime.h>
#include <stdint.h>

// QuantizationLayer: out[i, 4j + k] = bit (3-k) of rint(x[i,j]*16 - 0.5), as f32.
// R6 champion (one-shot grid, UNROLL=4, TPB=256, 128-bit .cs stores, input
// L2-resident across graph replays) with one change: input loads use __ldcg
// (L2-only, skip L1). L1 is flushed per launch so L1 allocation of the input
// buys nothing, but it competes with the 4x larger store stream for L1tex
// resources (L1 is the top-utilized unit in every profile).

#define TPB 256
#define UNROLL 4

__global__ void __launch_bounds__(TPB, 8)
quant_bits_kernel(const float* __restrict__ x, float* __restrict__ out, int n)
{
    int base = blockIdx.x * (TPB * UNROLL) + threadIdx.x;
    float4* out4 = reinterpret_cast<float4*>(out);

    // Front-batched independent L2-cached loads (skip L1; L2-resident across replays).
    float v[UNROLL];
#pragma unroll
    for (int u = 0; u < UNROLL; u++) {
        int i = base + u * TPB;
        v[u] = (i < n) ? __ldcg(&x[i]) : 0.0f;
    }

#pragma unroll
    for (int u = 0; u < UNROLL; u++) {
        int i = base + u * TPB;
        if (i >= n) continue;

        // Match JAX exactly: two separate f32 ops, round-half-even.
        float t = v[u] * 16.0f;
        t = t - 0.5f;
        int num = (int)rintf(t);
        num &= 255;  // uint8 wraparound emulation (no-op for x in [0,1))

        float4 bits;
        bits.x = (num & 8) ? 1.0f : 0.0f;
        bits.y = (num & 4) ? 1.0f : 0.0f;
        bits.z = (num & 2) ? 1.0f : 0.0f;
        bits.w = (num & 1) ? 1.0f : 0.0f;
        __stcs(out4 + i, bits);   // evict-first: don't displace L2-resident input
    }
}

extern "C" void kernel_launch(void* const* d_in, const int* in_sizes, int n_in,
                              void* d_out, int out_size)
{
    const float* x = (const float*)d_in[0];
    float* out = (float*)d_out;
    int n = in_sizes[0];   // 4096 * 2048 = 8388608

    int blocks = (n + TPB * UNROLL - 1) / (TPB * UNROLL);
    quant_bits_kernel<<<blocks, TPB>>>(x, out, n);
}